// round 16
// baseline (speedup 1.0000x reference)
#include <cuda_runtime.h>
#include <cuda_bf16.h>
#include <cstdint>

#define Bq 8
#define Nq 2048
#define Kq 32
#define C1q 64
#define C2q 128
#define GROUPS (Bq*Nq)        /* 16384 */
#define ROWS (GROUPS*Kq)      /* 524288 */
#define RAD2 (0.15f*0.15f)
#define EPSq 1e-5f

typedef unsigned long long u64;

// ---------------- scratch (device globals: allocation-free rule) ----------------
__device__ int      g_idx[GROUPS*Kq];                 // 2 MB
__device__ float    g_G[(size_t)GROUPS*C1q];          // 4 MB
__device__ float    g_P[(size_t)GROUPS*C1q];          // 4 MB
__device__ float    g_gsel[(size_t)GROUPS*C2q];       // 8 MB (max if gamma2>=0 else min)
__device__ uint32_t g_Bh[4096];                       // W2^T bf16-hi, SW128-swizzled image
__device__ uint32_t g_Bl[4096];                       // W2^T bf16-lo
__device__ float    g_stats1[2*C1q];
__device__ float    g_stats2[2*C2q];

// ---------------- helpers ----------------
__device__ __forceinline__ uint32_t smem_u32(const void* p) {
    uint32_t a;
    asm("{ .reg .u64 tmp; cvta.to.shared.u64 tmp, %1; cvt.u32.u64 %0, tmp; }"
        : "=r"(a) : "l"(p));
    return a;
}
__device__ __forceinline__ uint32_t prmt(uint32_t a, uint32_t b, uint32_t c) {
    uint32_t d;
    asm("prmt.b32 %0, %1, %2, %3;" : "=r"(d) : "r"(a), "r"(b), "r"(c));
    return d;
}
#define SW128(off) ((off) ^ (((off) >> 3) & 0x70))

#define CVTBF2(d, hi, lo) \
    asm("cvt.rn.bf16x2.f32 %0, %1, %2;" : "=r"(d) : "f"(hi), "f"(lo))

#define MMA16816(c, a, b0, b1) \
    asm volatile("mma.sync.aligned.m16n8k16.row.col.f32.bf16.bf16.f32 " \
        "{%0,%1,%2,%3}, {%4,%5,%6,%7}, {%8,%9}, {%0,%1,%2,%3};" \
        : "+f"((c)[0]), "+f"((c)[1]), "+f"((c)[2]), "+f"((c)[3]) \
        : "r"((a)[0]), "r"((a)[1]), "r"((a)[2]), "r"((a)[3]), "r"(b0), "r"(b1))

#define LDSM4(r, addr) \
    asm volatile("ldmatrix.sync.aligned.m8n8.x4.shared.b16 {%0,%1,%2,%3}, [%4];" \
        : "=r"((r)[0]), "=r"((r)[1]), "=r"((r)[2]), "=r"((r)[3]) : "r"(addr))

// ---------------- launch 1: zero stats accumulators ----------------
__global__ void zero_kernel() {
    int t = threadIdx.x;
    if (t < 128) g_stats1[t] = 0.f;
    g_stats2[t] = 0.f;
}

// ---------------- launch 2: per-point transforms + passthrough + W2 images ----------------
__global__ __launch_bounds__(256) void pw_kernel(const float* __restrict__ pos,
                                                 const float* __restrict__ feat,
                                                 const float* __restrict__ W1,
                                                 const float* __restrict__ W2,
                                                 float* __restrict__ out) {
    __shared__ float s_w[67*64];
    int t = threadIdx.x;
    for (int i = t; i < 67*64; i += 256) s_w[i] = W1[i];
    if (blockIdx.x < 192) {                // position passthrough
        int i = blockIdx.x*256 + t;
        out[i] = pos[i];
    }
    if (blockIdx.x < 16) {                 // swizzled bf16 hi/lo images of W2^T [n=128][k=64]
        int idx = blockIdx.x*256 + t;
        int n = idx >> 5, j = idx & 31;
        float w0 = W2[(2*j)*128 + n];
        float w1 = W2[(2*j+1)*128 + n];
        __nv_bfloat162 hi;
        hi.x = __float2bfloat16(w0);
        hi.y = __float2bfloat16(w1);
        __nv_bfloat162 lo;
        lo.x = __float2bfloat16(w0 - __bfloat162float(hi.x));
        lo.y = __float2bfloat16(w1 - __bfloat162float(hi.y));
        uint32_t off = (uint32_t)(n*128 + j*4);
        uint32_t sw = SW128(off) >> 2;
        g_Bh[sw] = *(uint32_t*)&hi;
        g_Bl[sw] = *(uint32_t*)&lo;
    }
    __syncthreads();
    int gi = blockIdx.x*256 + t;
    int p = gi >> 4, c = (gi & 15) * 4;
    const float* pp = pos + (size_t)p*3;
    float px = pp[0], py = pp[1], pz = pp[2];
    float4 w0 = *(const float4*)(s_w + 0*64 + c);
    float4 w1 = *(const float4*)(s_w + 1*64 + c);
    float4 w2 = *(const float4*)(s_w + 2*64 + c);
    float4 P;
    P.x = fmaf(pz, w2.x, fmaf(py, w1.x, px*w0.x));
    P.y = fmaf(pz, w2.y, fmaf(py, w1.y, px*w0.y));
    P.z = fmaf(pz, w2.z, fmaf(py, w1.z, px*w0.z));
    P.w = fmaf(pz, w2.w, fmaf(py, w1.w, px*w0.w));
    float4 G = P;
    const float* fr = feat + (size_t)p*64;
#pragma unroll 4
    for (int k = 0; k < 64; k += 4) {
        float4 f = *(const float4*)(fr + k);
#pragma unroll
        for (int kk = 0; kk < 4; kk++) {
            float fv = (&f.x)[kk];
            float4 w = *(const float4*)(s_w + (3+k+kk)*64 + c);
            G.x = fmaf(fv, w.x, G.x);
            G.y = fmaf(fv, w.y, G.y);
            G.z = fmaf(fv, w.z, G.z);
            G.w = fmaf(fv, w.w, G.w);
        }
    }
    *(float4*)(g_G + (size_t)p*64 + c) = G;
    *(float4*)(g_P + (size_t)p*64 + c) = P;
}

// ---------------- launch 3: ball query (8 centers/warp, shared candidate loads) + BN1 stats ----------------
__global__ __launch_bounds__(256) void bq_kernel(const float* __restrict__ pos) {
    __shared__ float4 s_pq[Nq];
    __shared__ int    s_idx[8][8][Kq];     // warp x center x K = 8 KB
    __shared__ float  s_part[8][128];
    int b = blockIdx.y;
    const float* pb = pos + (size_t)b*Nq*3;
    for (int i = threadIdx.x; i < Nq; i += 256) {
        float x = pb[3*i], y = pb[3*i+1], z = pb[3*i+2];
        s_pq[i] = make_float4(x, y, z, x*x + y*y + z*z);
    }
    __syncthreads();
    int w = threadIdx.x >> 5, lane = threadIdx.x & 31;
    unsigned lmask = (1u << lane) - 1u;
    int j0 = blockIdx.x*64 + w*8;
    float4 cc[8];
#pragma unroll
    for (int i = 0; i < 8; i++) cc[i] = s_pq[j0 + i];   // broadcast reads
    int cnt[8];
#pragma unroll
    for (int i = 0; i < 8; i++) cnt[i] = 0;
    // shared candidate stream: one LDS.128 serves all 8 centers
    for (int base = 0; base < Nq; base += 32) {
        float4 q = s_pq[base + lane];
#pragma unroll
        for (int i = 0; i < 8; i++) {
            // identical per-candidate arithmetic to prior validated versions
            float d = cc[i].w + q.w - 2.0f*(cc[i].x*q.x + cc[i].y*q.y + cc[i].z*q.z);
            bool v = !(d > RAD2);
            unsigned m = __ballot_sync(0xffffffffu, v);
            int p = cnt[i] + __popc(m & lmask);
            if (v && p < Kq) s_idx[w][i][p] = base + lane;
            cnt[i] += __popc(m);
        }
    }
    __syncwarp();
    // per center: emit indices + fused stats gather
    int c4 = (lane & 15) * 4;
    const float* Gb = g_G + (((size_t)b*Nq) << 6);
    float sum[4] = {0.f,0.f,0.f,0.f}, sq[4] = {0.f,0.f,0.f,0.f};
#pragma unroll
    for (int i = 0; i < 8; i++) {
        int j = j0 + i;
        int first = s_idx[w][i][0];
        int nvalid = cnt[i] < Kq ? cnt[i] : Kq;
        int val = (lane < nvalid) ? s_idx[w][i][lane] : first;
        g_idx[((size_t)b*Nq + j)*Kq + lane] = val;
        float4 p4 = *(const float4*)(g_P + (((size_t)b*Nq + j) << 6) + c4);
#pragma unroll 4
        for (int k = 0; k < 16; k++) {
            int nbA = __shfl_sync(0xffffffffu, val, 2*k);
            int nbB = __shfl_sync(0xffffffffu, val, 2*k+1);
            int nb = (lane < 16) ? nbA : nbB;
            float4 g4 = *(const float4*)(Gb + ((size_t)nb << 6) + c4);
            float h0 = g4.x - p4.x, h1 = g4.y - p4.y;
            float h2 = g4.z - p4.z, h3 = g4.w - p4.w;
            sum[0] += h0; sum[1] += h1; sum[2] += h2; sum[3] += h3;
            sq[0] = fmaf(h0,h0,sq[0]); sq[1] = fmaf(h1,h1,sq[1]);
            sq[2] = fmaf(h2,h2,sq[2]); sq[3] = fmaf(h3,h3,sq[3]);
        }
        __syncwarp();
    }
#pragma unroll
    for (int j = 0; j < 4; j++) {
        sum[j] += __shfl_xor_sync(0xffffffffu, sum[j], 16);
        sq[j]  += __shfl_xor_sync(0xffffffffu, sq[j],  16);
    }
    if (lane < 16) {
#pragma unroll
        for (int j = 0; j < 4; j++) {
            s_part[w][c4 + j]      = sum[j];
            s_part[w][64 + c4 + j] = sq[j];
        }
    }
    __syncthreads();
    int t = threadIdx.x;
    if (t < 128) {
        float v = 0.f;
#pragma unroll
        for (int w2 = 0; w2 < 8; w2++) v += s_part[w2][t];
        atomicAdd(&g_stats1[t], v);
    }
}

// ---------------- launch 4: bf16-split mma.sync GEMM2 (fin1 inlined, 2 tiles/CTA) ----------------
#define SM_AH 0
#define SM_AL 16384
#define SM_BH 32768
#define SM_BL 49152
#define SM_STAT 65536        /* 256 floats */
#define SM_SC   66560        /* 128 floats */
#define SM_G2   67072        /* 128 floats: gamma2 (sign selects max/min) */
#define SM_IDX  67584        /* 128 ints: idx stage for next tile */
#define SM_SCR  68096        /* 8 warps x 2560 B epilogue scratch */
#define GEMM2_SMEM (68096 + 20480)   /* 88576 B */

__global__ __launch_bounds__(256, 2) void gemm2_kernel(const float* __restrict__ g1,
                                                       const float* __restrict__ b1,
                                                       const float* __restrict__ g2) {
    extern __shared__ char smem[];
    uint32_t sb = smem_u32(smem);
    float* s_stat  = (float*)(smem + SM_STAT);
    float* s_sc    = (float*)(smem + SM_SC);
    float* s_g2    = (float*)(smem + SM_G2);
    int*   s_idxst = (int*)(smem + SM_IDX);
    int t = threadIdx.x, w = t >> 5, L = t & 31;

    {   // copy prebuilt swizzled W2^T bf16 images (16 KB each)
        float4* dh = (float4*)(smem + SM_BH);
        float4* dl = (float4*)(smem + SM_BL);
        const float4* shp = (const float4*)g_Bh;
        const float4* slp = (const float4*)g_Bl;
#pragma unroll
        for (int j = 0; j < 4; j++) {
            dh[t + 256*j] = shp[t + 256*j];
            dl[t + 256*j] = slp[t + 256*j];
        }
    }
    if (t < 64) {                          // fin1 inline: BN1 scale/shift from g_stats1
        float inv = 1.0f / (float)ROWS;
        float mean = g_stats1[t] * inv;
        float var  = g_stats1[C1q + t] * inv - mean*mean;
        float sc   = g1[t] * rsqrtf(var + EPSq);
        s_sc[t] = sc;
        s_sc[C1q + t] = b1[t] - mean*sc;
    }
    if (t < 128) s_g2[t] = g2[t];
    s_stat[t] = 0.f;
    if (t < 128)                           // stage tile 0 indices
        s_idxst[t] = g_idx[(size_t)(blockIdx.x*8)*32 + t];

    int g = w & 3, nb = (w >> 2) * 64;
    uint32_t xorv = (uint32_t)((L & 7) * 16);
    uint32_t aoff = (uint32_t)((g*32 + (L & 15))*128 + (L >> 4)*16);
    int nbase = nb + (L & 7) + ((L & 16) ? 8 : 0);
    uint32_t boff = (uint32_t)(nbase*128 + ((L & 8) ? 16 : 0));
    int r = L & 3;
    float2* scr2 = (float2*)(smem + SM_SCR + w*2560);   // per-warp [64 ch][4+1 pad] float2

    for (int T = 0; T < 2; T++) {
        int gbase = blockIdx.x*8 + T*4;
        __syncthreads();                  // A free (prior mainloop done); smem init/stage ready
        // ---- gather + BN1 + ReLU + truncation hi/lo split -> swizzled A tiles ----
#pragma unroll
        for (int j = 0; j < 8; j++) {
            int i = t + 256*j;
            int g2i = i >> 9, rr = (i >> 4) & 31, c = (i & 15) * 4;
            int gg = gbase + g2i;
            int b = gg >> 11;
            int nbi = s_idxst[g2i*32 + rr];
            float4 g4 = *(const float4*)(g_G + (((size_t)(b << 11) + nbi) << 6) + c);
            float4 p4 = *(const float4*)(g_P + ((size_t)gg << 6) + c);
            float h0 = fmaxf(fmaf(g4.x - p4.x, s_sc[c+0], s_sc[64+c+0]), 0.f);
            float h1 = fmaxf(fmaf(g4.y - p4.y, s_sc[c+1], s_sc[64+c+1]), 0.f);
            float h2 = fmaxf(fmaf(g4.z - p4.z, s_sc[c+2], s_sc[64+c+2]), 0.f);
            float h3 = fmaxf(fmaf(g4.w - p4.w, s_sc[c+3], s_sc[64+c+3]), 0.f);
            uint32_t u0 = __float_as_uint(h0), u1 = __float_as_uint(h1);
            uint32_t u2 = __float_as_uint(h2), u3 = __float_as_uint(h3);
            uint32_t ha = prmt(u0, u1, 0x7632);       // truncated bf16 pair (h>=0)
            uint32_t hb = prmt(u2, u3, 0x7632);
            float l0 = h0 - __uint_as_float(u0 & 0xFFFF0000u);
            float l1 = h1 - __uint_as_float(u1 & 0xFFFF0000u);
            float l2 = h2 - __uint_as_float(u2 & 0xFFFF0000u);
            float l3 = h3 - __uint_as_float(u3 & 0xFFFF0000u);
            uint32_t la, lb;
            CVTBF2(la, l1, l0);
            CVTBF2(lb, l3, l2);
            int row = g2i*32 + rr;
            uint32_t sw = SW128((uint32_t)(row*128 + c*2));
            *(uint2*)(smem + SM_AH + sw) = make_uint2(ha, hb);
            *(uint2*)(smem + SM_AL + sw) = make_uint2(la, lb);
        }
        __syncthreads();
        if (T == 0 && t < 128)            // stage next tile's indices (hidden under mainloop)
            s_idxst[t] = g_idx[(size_t)(gbase + 4)*32 + t];

        // ---- mainloop ----
        float acc[2][8][4];
#pragma unroll
        for (int i = 0; i < 2; i++)
#pragma unroll
            for (int n = 0; n < 8; n++)
#pragma unroll
                for (int q = 0; q < 4; q++) acc[i][n][q] = 0.f;

#pragma unroll
        for (int ks = 0; ks < 4; ks++) {
            uint32_t ah[2][4], al[2][4];
#pragma unroll
            for (int i = 0; i < 2; i++) {
                uint32_t lin = aoff + (uint32_t)(i*2048 + ks*32);
                LDSM4(ah[i], sb + SM_AH + (lin ^ xorv));
                LDSM4(al[i], sb + SM_AL + (lin ^ xorv));
            }
#pragma unroll
            for (int p = 0; p < 4; p++) {
                uint32_t lin = boff + (uint32_t)(p*2048 + ks*32);
                uint32_t bh[4], bl[4];
                LDSM4(bh, sb + SM_BH + (lin ^ xorv));
                LDSM4(bl, sb + SM_BL + (lin ^ xorv));
#pragma unroll
                for (int i = 0; i < 2; i++) {
#pragma unroll
                    for (int q = 0; q < 2; q++) {
                        float* c4p = acc[i][2*p + q];
                        MMA16816(c4p, ah[i], bh[2*q], bh[2*q+1]);
                        MMA16816(c4p, ah[i], bl[2*q], bl[2*q+1]);
                        MMA16816(c4p, al[i], bh[2*q], bh[2*q+1]);
                    }
                }
            }
        }

        // ---- epilogue: warp-asynchronous (dedicated scratch, no block barrier) ----
        int ge = gbase + g;
        // pass A: max/min -> single selected store (sign(gamma2) picks which)
#pragma unroll
        for (int nt = 0; nt < 8; nt++) {
#pragma unroll
            for (int j = 0; j < 2; j++) {
                float v0 = acc[0][nt][j], v1 = acc[0][nt][j+2];
                float v2 = acc[1][nt][j], v3 = acc[1][nt][j+2];
                float mx = fmaxf(fmaxf(v0, v1), fmaxf(v2, v3));
                float mn = fminf(fminf(v0, v1), fminf(v2, v3));
                mx = fmaxf(mx, __shfl_xor_sync(0xffffffffu, mx, 16));
                mn = fminf(mn, __shfl_xor_sync(0xffffffffu, mn, 16));
                if (L < 16) scr2[(nt*8 + 2*r + j)*5 + (L >> 2)] = make_float2(mx, mn);
            }
        }
        __syncwarp();
#pragma unroll
        for (int cp = 0; cp < 2; cp++) {
            int chl = L + cp*32;
            float2 e0 = scr2[chl*5+0], e1 = scr2[chl*5+1];
            float2 e2 = scr2[chl*5+2], e3 = scr2[chl*5+3];
            float mx = fmaxf(fmaxf(e0.x, e1.x), fmaxf(e2.x, e3.x));
            float mn = fminf(fminf(e0.y, e1.y), fminf(e2.y, e3.y));
            g_gsel[(size_t)ge*C2q + nb + chl] = (s_g2[nb + chl] >= 0.f) ? mx : mn;
        }
        __syncwarp();
        // pass B: sum/sumsq
#pragma unroll
        for (int nt = 0; nt < 8; nt++) {
#pragma unroll
            for (int j = 0; j < 2; j++) {
                float v0 = acc[0][nt][j], v1 = acc[0][nt][j+2];
                float v2 = acc[1][nt][j], v3 = acc[1][nt][j+2];
                float s  = (v0 + v1) + (v2 + v3);
                float s2 = fmaf(v0, v0, fmaf(v1, v1, fmaf(v2, v2, v3*v3)));
                s  += __shfl_xor_sync(0xffffffffu, s,  16);
                s2 += __shfl_xor_sync(0xffffffffu, s2, 16);
                if (L < 16) scr2[(nt*8 + 2*r + j)*5 + (L >> 2)] = make_float2(s, s2);
            }
        }
        __syncwarp();
#pragma unroll
        for (int cp = 0; cp < 2; cp++) {
            int chl = L + cp*32;
            float2 e0 = scr2[chl*5+0], e1 = scr2[chl*5+1];
            float2 e2 = scr2[chl*5+2], e3 = scr2[chl*5+3];
            atomicAdd(&s_stat[nb + chl],       (e0.x + e1.x) + (e2.x + e3.x));
            atomicAdd(&s_stat[128 + nb + chl], (e0.y + e1.y) + (e2.y + e3.y));
        }
        // loop-top __syncthreads guards A reuse by next gather
    }
    __syncthreads();
    atomicAdd(&g_stats2[t], s_stat[t]);    // [0..127]=sum, [128..255]=sumsq
}

// ---------------- launch 5: finalize output (fin2 inlined; single selected stream) ----------------
__global__ __launch_bounds__(128) void final_kernel(const float* __restrict__ g2,
                                                    const float* __restrict__ b2,
                                                    float* __restrict__ out) {
    int c = threadIdx.x;
    float inv = 1.0f / (float)ROWS;
    float mean = g_stats2[c] * inv;
    float var  = g_stats2[C2q + c] * inv - mean*mean;
    float scale = g2[c] * rsqrtf(var + EPSq);
    float shift = b2[c] - mean*scale;
    for (int g = 0; g < 16; g++) {
        size_t gg = (size_t)blockIdx.x*16 + g;
        out[gg*C2q + c] = fmaxf(fmaf(g_gsel[gg*C2q + c], scale, shift), 0.f);
    }
}

extern "C" void kernel_launch(void* const* d_in, const int* in_sizes, int n_in,
                              void* d_out, int out_size) {
    (void)in_sizes; (void)n_in; (void)out_size;
    const float* pos  = (const float*)d_in[0];
    const float* feat = (const float*)d_in[1];
    const float* W1   = (const float*)d_in[2];
    const float* g1   = (const float*)d_in[3];
    const float* b1   = (const float*)d_in[4];
    const float* W2   = (const float*)d_in[5];
    const float* g2   = (const float*)d_in[6];
    const float* b2   = (const float*)d_in[7];
    float* out = (float*)d_out;

    cudaFuncSetAttribute(gemm2_kernel, cudaFuncAttributeMaxDynamicSharedMemorySize, GEMM2_SMEM);

    zero_kernel<<<1, 256>>>();                                 // 1
    pw_kernel<<<GROUPS*16/256, 256>>>(pos, feat, W1, W2, out); // 2
    bq_kernel<<<dim3(Nq/64, Bq), 256>>>(pos);                  // 3
    gemm2_kernel<<<GROUPS/8, 256, GEMM2_SMEM>>>(g1, b1, g2);   // 4  <- profiled slot
    final_kernel<<<GROUPS/16, 128>>>(g2, b2, out + (size_t)Bq*Nq*3); // 5
}